// round 11
// baseline (speedup 1.0000x reference)
#include <cuda_runtime.h>

#define IMG     512
#define NIMG    32
#define WIN     11
#define TILE_W  32
#define TILE_H  54
#define INH     (TILE_H + WIN - 1)   // 64 haloed rows (exactly 256 h-tasks)
#define HSTRIDE 34                   // even u64 stride: 16B-aligned row starts
#define NTHREADS 256
#define GRID_Y  ((IMG + TILE_H - 1) / TILE_H)     // 10
#define NBLOCKS (16 * GRID_Y * 32)                // 5120 CTAs

typedef unsigned long long u64;

__device__ double       g_acc   = 0.0;
__device__ unsigned int g_count = 0u;

__device__ __forceinline__ u64 pack2(float a, float b) {
    u64 r; asm("mov.b64 %0, {%1,%2};" : "=l"(r) : "f"(a), "f"(b)); return r;
}
__device__ __forceinline__ void unpack2(u64 v, float &a, float &b) {
    asm("mov.b64 {%0,%1}, %2;" : "=f"(a), "=f"(b) : "l"(v));
}
__device__ __forceinline__ u64 fma2(u64 a, u64 b, u64 c) {
    u64 d; asm("fma.rn.f32x2 %0, %1, %2, %3;" : "=l"(d) : "l"(a), "l"(b), "l"(c)); return d;
}
__device__ __forceinline__ u64 mul2(u64 a, u64 b) {
    u64 d; asm("mul.rn.f32x2 %0, %1, %2;" : "=l"(d) : "l"(a), "l"(b)); return d;
}

// Normalized 1D Gaussian taps, win=11, sigma=1.5 (standard SSIM window, symmetric).
#define G0 0.00102838f
#define G1 0.00759876f
#define G2 0.03600077f
#define G3 0.10936069f
#define G4 0.21300553f
#define G5 0.26601172f

__global__ void __launch_bounds__(NTHREADS, 4)
ssim_main_kernel(const float* __restrict__ x,
                 const float* __restrict__ y,
                 float* __restrict__ out)
{
    __shared__ u64   hmu[INH * HSTRIDE];   // h-conv packed {mu_s, mu_d}
    __shared__ u64   hsq[INH * HSTRIDE];   // h-conv packed {E[s2], E[d2]}
    __shared__ float warpsum[NTHREADS / 32];

    const int tid = threadIdx.x;

    const u64 gg[6] = { pack2(G0,G0), pack2(G1,G1), pack2(G2,G2),
                        pack2(G3,G3), pack2(G4,G4), pack2(G5,G5) };
#define GG(k) gg[(k) < 6 ? (k) : 10 - (k)]

    const int n      = blockIdx.z;
    const int tile_x = blockIdx.x * TILE_W;
    const int tile_y = blockIdx.y * TILE_H;
    const float* __restrict__ xb = x + (size_t)n * IMG * IMG;
    const float* __restrict__ yb = y + (size_t)n * IMG * IMG;

    // ---- Stage B: horizontal pass. 64 rows x 4 segments of 8 outputs = 256 tasks,
    // exactly one per thread. Inputs stream straight from global (L1-resident).
    {
        const int row = tid >> 2;                // 0..63 (haloed row)
        const int s0  = (tid & 3) * 8;           // output segment start
        const int gr  = tile_y + row - WIN / 2;
        const int gc0 = tile_x + s0 - WIN / 2;   // first needed input col
        const int gcr = tile_x + s0 - 8;         // 8-aligned vector base (= gc0-3)

        u64 amu[8], asq[8];
        #pragma unroll
        for (int o = 0; o < 8; o++) { amu[o] = 0ull; asq[o] = 0ull; }

        if ((unsigned)gr < IMG) {
            const float* __restrict__ xr = xb + gr * IMG;
            const float* __restrict__ yr = yb + gr * IMG;
            if (gcr >= 0 && gcr + 23 < IMG) {
                const float4* __restrict__ xr4 = (const float4*)(xr + gcr);
                const float4* __restrict__ yr4 = (const float4*)(yr + gcr);
                #pragma unroll
                for (int q = 0; q < 6; q++) {
                    const float4 xv = xr4[q];
                    const float4 yv = yr4[q];
                    const float xe[4] = {xv.x, xv.y, xv.z, xv.w};
                    const float ye[4] = {yv.x, yv.y, yv.z, yv.w};
                    #pragma unroll
                    for (int e = 0; e < 4; e++) {
                        const int t = 4 * q + e - 3;   // input index in 18-window
                        if (t < 0 || t > 17) continue;
                        const u64 p  = pack2(xe[e] + ye[e], xe[e] - ye[e]);
                        const u64 p2 = mul2(p, p);
                        #pragma unroll
                        for (int o = 0; o < 8; o++) {
                            const int k = t - o;
                            if (k >= 0 && k < WIN) {
                                amu[o] = fma2(GG(k), p,  amu[o]);
                                asq[o] = fma2(GG(k), p2, asq[o]);
                            }
                        }
                    }
                }
            } else {
                #pragma unroll
                for (int t = 0; t < 18; t++) {
                    const int gc = gc0 + t;
                    float vx = 0.f, vy = 0.f;
                    if ((unsigned)gc < IMG) { vx = xr[gc]; vy = yr[gc]; }
                    const u64 p  = pack2(vx + vy, vx - vy);
                    const u64 p2 = mul2(p, p);
                    #pragma unroll
                    for (int o = 0; o < 8; o++) {
                        const int k = t - o;
                        if (k >= 0 && k < WIN) {
                            amu[o] = fma2(GG(k), p,  amu[o]);
                            asq[o] = fma2(GG(k), p2, asq[o]);
                        }
                    }
                }
            }
        }
        // STS.128 pairs: (row*34 + s0 + even) is even -> 16B aligned
        #pragma unroll
        for (int o = 0; o < 8; o += 2) {
            *(ulonglong2*)&hmu[row * HSTRIDE + s0 + o] = make_ulonglong2(amu[o], amu[o + 1]);
            *(ulonglong2*)&hsq[row * HSTRIDE + s0 + o] = make_ulonglong2(asq[o], asq[o + 1]);
        }
    }
    __syncthreads();

    // ---- Stage C: vertical pass + SSIM. 8 segments x 32 cols = 256 threads.
    // Segments 0..5 own 7 rows (read 17), segments 6..7 own 6 rows (read 16).
    const float C1  = 1e-4f;
    const float C2  = 9e-4f;
    const float EPS = 1e-8f;

    float local = 0.f;
    {
        const int col  = tid & 31;
        const int seg  = tid >> 5;                         // 0..7 (warp-uniform)
        const int r0   = (seg < 6) ? seg * 7 : 42 + (seg - 6) * 6;
        const int nout = (seg < 6) ? 7 : 6;

        // Warp-uniform dead-work skip: on the partial last y-tile, segments whose
        // whole output range is below the image bottom produce nothing.
        if (tile_y + r0 < IMG) {
            u64 vmu[7], vsq[7];
            #pragma unroll
            for (int o = 0; o < 7; o++) { vmu[o] = 0ull; vsq[o] = 0ull; }

            #pragma unroll
            for (int i = 0; i < 17; i++) {
                if (i == 16 && nout == 6) break;           // warp-uniform early out
                const u64 m = hmu[(r0 + i) * HSTRIDE + col];
                const u64 q = hsq[(r0 + i) * HSTRIDE + col];
                #pragma unroll
                for (int o = 0; o < 7; o++) {
                    const int k = i - o;
                    if (k >= 0 && k < WIN) {
                        vmu[o] = fma2(GG(k), m, vmu[o]);
                        vsq[o] = fma2(GG(k), q, vsq[o]);
                    }
                }
            }

            #pragma unroll
            for (int o = 0; o < 7; o++) {
                if (o < nout && (tile_y + r0 + o) < IMG) {
                    float a, b, e, f;
                    const u64 q2 = mul2(vmu[o], vmu[o]);   // {mu_s^2, mu_d^2}
                    unpack2(q2, a, b);
                    unpack2(vsq[o], e, f);                 // {E[s2], E[d2]}
                    const float P  = 0.5f * (a - b);       // 2*mu_x*mu_y
                    const float Qm = 0.5f * (a + b);       // mu_x^2 + mu_y^2
                    const float R  = 0.5f * (e - f) - P;   // 2*sig_xy
                    const float S  = 0.5f * (e + f) - Qm;  // sig_x^2 + sig_y^2
                    const float num = (P + C1) * (R + C2);
                    const float den = (Qm + C1) * (S + C2);
                    local += __saturatef(__fdividef(num, den + EPS));
                }
            }
        }
    }

    // ---- Block reduction
    #pragma unroll
    for (int off = 16; off; off >>= 1)
        local += __shfl_down_sync(0xffffffffu, local, off);
    if ((tid & 31) == 0) warpsum[tid >> 5] = local;
    __syncthreads();

    // ---- Fused finale: self-resetting device accumulator, last CTA writes out.
    if (tid == 0) {
        float s = 0.f;
        #pragma unroll
        for (int i = 0; i < NTHREADS / 32; i++) s += warpsum[i];
        atomicAdd(&g_acc, (double)s);
        __threadfence();
        const unsigned done = atomicAdd(&g_count, 1u);
        if (done == NBLOCKS - 1) {
            __threadfence();
            const double v = *(volatile double*)&g_acc;
            out[0] = (float)(v / ((double)NIMG * IMG * IMG));
            *(volatile double*)&g_acc = 0.0;            // reset for next replay
            __threadfence();
            *(volatile unsigned*)&g_count = 0u;
        }
    }
}

extern "C" void kernel_launch(void* const* d_in, const int* in_sizes, int n_in,
                              void* d_out, int out_size)
{
    const float* x = (const float*)d_in[0];
    const float* y = (const float*)d_in[1];
    float* out = (float*)d_out;

    dim3 grid(IMG / TILE_W, GRID_Y, NIMG);   // 16 x 10 x 32 = 5120 CTAs
    ssim_main_kernel<<<grid, NTHREADS>>>(x, y, out);
}

// round 12
// speedup vs baseline: 1.0137x; 1.0137x over previous
#include <cuda_runtime.h>

#define IMG     512
#define NIMG    32
#define WIN     11
#define TILE_W  32
#define TILE_H  54
#define INH     (TILE_H + WIN - 1)   // 64 haloed rows (exactly 256 h-tasks)
#define HSTRIDE 34                   // even u64 stride: 16B-aligned row starts
#define NTHREADS 256
#define GRID_Y  ((IMG + TILE_H - 1) / TILE_H)     // 10
#define NBLOCKS (16 * GRID_Y * 32)                // 5120 CTAs

typedef unsigned long long u64;

__device__ double       g_acc   = 0.0;
__device__ unsigned int g_count = 0u;

// Normalized 1D Gaussian taps, win=11, sigma=1.5 (standard SSIM window, symmetric).
// Stored packed {g,g} in constant memory -> LDCU (UR dest) -> FFMA2 with uniform
// operand escapes the RF-banking rt=3 penalty.
#define G0 0.00102838f
#define G1 0.00759876f
#define G2 0.03600077f
#define G3 0.10936069f
#define G4 0.21300553f
#define G5 0.26601172f
__constant__ float2 c_taps[6] = {
    {G0, G0}, {G1, G1}, {G2, G2}, {G3, G3}, {G4, G4}, {G5, G5}
};

__device__ __forceinline__ u64 pack2(float a, float b) {
    u64 r; asm("mov.b64 %0, {%1,%2};" : "=l"(r) : "f"(a), "f"(b)); return r;
}
__device__ __forceinline__ void unpack2(u64 v, float &a, float &b) {
    asm("mov.b64 {%0,%1}, %2;" : "=f"(a), "=f"(b) : "l"(v));
}
__device__ __forceinline__ u64 fma2(u64 a, u64 b, u64 c) {
    u64 d; asm("fma.rn.f32x2 %0, %1, %2, %3;" : "=l"(d) : "l"(a), "l"(b), "l"(c)); return d;
}
__device__ __forceinline__ u64 mul2(u64 a, u64 b) {
    u64 d; asm("mul.rn.f32x2 %0, %1, %2;" : "=l"(d) : "l"(a), "l"(b)); return d;
}

// Compile-time-constant index into constant memory (after unroll) -> ld.const.u64
// at a fixed offset; uniform across the warp -> UR promotion candidate.
__device__ __forceinline__ u64 tap_u64(int k6) {
    return reinterpret_cast<const u64*>(c_taps)[k6];
}
#define GG(k) tap_u64((k) < 6 ? (k) : 10 - (k))

__global__ void __launch_bounds__(NTHREADS, 4)
ssim_main_kernel(const float* __restrict__ x,
                 const float* __restrict__ y,
                 float* __restrict__ out)
{
    __shared__ u64   hmu[INH * HSTRIDE];   // h-conv packed {mu_s, mu_d}
    __shared__ u64   hsq[INH * HSTRIDE];   // h-conv packed {E[s2], E[d2]}
    __shared__ float warpsum[NTHREADS / 32];

    const int tid = threadIdx.x;

    const int n      = blockIdx.z;
    const int tile_x = blockIdx.x * TILE_W;
    const int tile_y = blockIdx.y * TILE_H;
    const float* __restrict__ xb = x + (size_t)n * IMG * IMG;
    const float* __restrict__ yb = y + (size_t)n * IMG * IMG;

    // ---- Stage B: horizontal pass. 64 rows x 4 segments of 8 outputs = 256 tasks,
    // exactly one per thread. Inputs stream straight from global (L1-resident).
    {
        const int row = tid >> 2;                // 0..63 (haloed row)
        const int s0  = (tid & 3) * 8;           // output segment start
        const int gr  = tile_y + row - WIN / 2;
        const int gc0 = tile_x + s0 - WIN / 2;   // first needed input col
        const int gcr = tile_x + s0 - 8;         // 8-aligned vector base (= gc0-3)

        u64 amu[8], asq[8];
        #pragma unroll
        for (int o = 0; o < 8; o++) { amu[o] = 0ull; asq[o] = 0ull; }

        if ((unsigned)gr < IMG) {
            const float* __restrict__ xr = xb + gr * IMG;
            const float* __restrict__ yr = yb + gr * IMG;
            if (gcr >= 0 && gcr + 23 < IMG) {
                const float4* __restrict__ xr4 = (const float4*)(xr + gcr);
                const float4* __restrict__ yr4 = (const float4*)(yr + gcr);
                #pragma unroll
                for (int q = 0; q < 6; q++) {
                    const float4 xv = xr4[q];
                    const float4 yv = yr4[q];
                    const float xe[4] = {xv.x, xv.y, xv.z, xv.w};
                    const float ye[4] = {yv.x, yv.y, yv.z, yv.w};
                    #pragma unroll
                    for (int e = 0; e < 4; e++) {
                        const int t = 4 * q + e - 3;   // input index in 18-window
                        if (t < 0 || t > 17) continue;
                        const u64 p  = pack2(xe[e] + ye[e], xe[e] - ye[e]);
                        const u64 p2 = mul2(p, p);
                        #pragma unroll
                        for (int o = 0; o < 8; o++) {
                            const int k = t - o;
                            if (k >= 0 && k < WIN) {
                                amu[o] = fma2(GG(k), p,  amu[o]);
                                asq[o] = fma2(GG(k), p2, asq[o]);
                            }
                        }
                    }
                }
            } else {
                #pragma unroll
                for (int t = 0; t < 18; t++) {
                    const int gc = gc0 + t;
                    float vx = 0.f, vy = 0.f;
                    if ((unsigned)gc < IMG) { vx = xr[gc]; vy = yr[gc]; }
                    const u64 p  = pack2(vx + vy, vx - vy);
                    const u64 p2 = mul2(p, p);
                    #pragma unroll
                    for (int o = 0; o < 8; o++) {
                        const int k = t - o;
                        if (k >= 0 && k < WIN) {
                            amu[o] = fma2(GG(k), p,  amu[o]);
                            asq[o] = fma2(GG(k), p2, asq[o]);
                        }
                    }
                }
            }
        }
        // STS.128 pairs: (row*34 + s0 + even) is even -> 16B aligned
        #pragma unroll
        for (int o = 0; o < 8; o += 2) {
            *(ulonglong2*)&hmu[row * HSTRIDE + s0 + o] = make_ulonglong2(amu[o], amu[o + 1]);
            *(ulonglong2*)&hsq[row * HSTRIDE + s0 + o] = make_ulonglong2(asq[o], asq[o + 1]);
        }
    }
    __syncthreads();

    // ---- Stage C: vertical pass + SSIM. 8 segments x 32 cols = 256 threads.
    // Segments 0..5 own 7 rows (read 17), segments 6..7 own 6 rows (read 16).
    const float C1  = 1e-4f;
    const float C2  = 9e-4f;
    const float EPS = 1e-8f;

    float local = 0.f;
    {
        const int col  = tid & 31;
        const int seg  = tid >> 5;                         // 0..7 (warp-uniform)
        const int r0   = (seg < 6) ? seg * 7 : 42 + (seg - 6) * 6;
        const int nout = (seg < 6) ? 7 : 6;

        // Warp-uniform dead-work skip on the partial last y-tile.
        if (tile_y + r0 < IMG) {
            u64 vmu[7], vsq[7];
            #pragma unroll
            for (int o = 0; o < 7; o++) { vmu[o] = 0ull; vsq[o] = 0ull; }

            #pragma unroll
            for (int i = 0; i < 17; i++) {
                if (i == 16 && nout == 6) break;           // warp-uniform early out
                const u64 m = hmu[(r0 + i) * HSTRIDE + col];
                const u64 q = hsq[(r0 + i) * HSTRIDE + col];
                #pragma unroll
                for (int o = 0; o < 7; o++) {
                    const int k = i - o;
                    if (k >= 0 && k < WIN) {
                        vmu[o] = fma2(GG(k), m, vmu[o]);
                        vsq[o] = fma2(GG(k), q, vsq[o]);
                    }
                }
            }

            #pragma unroll
            for (int o = 0; o < 7; o++) {
                if (o < nout && (tile_y + r0 + o) < IMG) {
                    float a, b, e, f;
                    const u64 q2 = mul2(vmu[o], vmu[o]);   // {mu_s^2, mu_d^2}
                    unpack2(q2, a, b);
                    unpack2(vsq[o], e, f);                 // {E[s2], E[d2]}
                    const float P  = 0.5f * (a - b);       // 2*mu_x*mu_y
                    const float Qm = 0.5f * (a + b);       // mu_x^2 + mu_y^2
                    const float R  = 0.5f * (e - f) - P;   // 2*sig_xy
                    const float S  = 0.5f * (e + f) - Qm;  // sig_x^2 + sig_y^2
                    const float num = (P + C1) * (R + C2);
                    const float den = (Qm + C1) * (S + C2);
                    local += __saturatef(__fdividef(num, den + EPS));
                }
            }
        }
    }

    // ---- Block reduction
    #pragma unroll
    for (int off = 16; off; off >>= 1)
        local += __shfl_down_sync(0xffffffffu, local, off);
    if ((tid & 31) == 0) warpsum[tid >> 5] = local;
    __syncthreads();

    // ---- Fused finale: self-resetting device accumulator, last CTA writes out.
    if (tid == 0) {
        float s = 0.f;
        #pragma unroll
        for (int i = 0; i < NTHREADS / 32; i++) s += warpsum[i];
        atomicAdd(&g_acc, (double)s);
        __threadfence();
        const unsigned done = atomicAdd(&g_count, 1u);
        if (done == NBLOCKS - 1) {
            __threadfence();
            const double v = *(volatile double*)&g_acc;
            out[0] = (float)(v / ((double)NIMG * IMG * IMG));
            *(volatile double*)&g_acc = 0.0;            // reset for next replay
            __threadfence();
            *(volatile unsigned*)&g_count = 0u;
        }
    }
}

extern "C" void kernel_launch(void* const* d_in, const int* in_sizes, int n_in,
                              void* d_out, int out_size)
{
    const float* x = (const float*)d_in[0];
    const float* y = (const float*)d_in[1];
    float* out = (float*)d_out;

    dim3 grid(IMG / TILE_W, GRID_Y, NIMG);   // 16 x 10 x 32 = 5120 CTAs
    ssim_main_kernel<<<grid, NTHREADS>>>(x, y, out);
}